// round 16
// baseline (speedup 1.0000x reference)
#include <cuda_runtime.h>
#include <cuda_fp16.h>
#include <cstdint>

#define BATCH 8
#define CCH   512
#define NPIX  1024
#define QKVC  1536
#define BHTOT 64
#define EPSLN 1e-5f
#define SCALEF 0.125f

// Scratch (device globals: allocation-free contract)
__device__ __half g_xnh [(size_t)BATCH * NPIX * CCH];   // [b][n][c]  LN out (half)
__device__ __half g_qkvt[(size_t)BATCH * NPIX * QKVC];  // [b][n][o]  qkv^T (half)
__device__ __half g_atth[(size_t)BATCH * NPIX * CCH];   // [b][n][hc] attn out (half)
__device__ __half g_wqkvh[QKVC * CCH];
__device__ __half g_wouth[CCH * CCH];

// ---------------------------------------------------------------------------
// fp16 mma.sync helpers (fragment maps validated R10/R12 on hardware)
// ---------------------------------------------------------------------------
__device__ __forceinline__ void mma16(float* c, const unsigned* a, const unsigned* b) {
    asm volatile("mma.sync.aligned.m16n8k16.row.col.f32.f16.f16.f32 "
        "{%0,%1,%2,%3}, {%4,%5,%6,%7}, {%8,%9}, {%0,%1,%2,%3};"
        : "+f"(c[0]), "+f"(c[1]), "+f"(c[2]), "+f"(c[3])
        : "r"(a[0]), "r"(a[1]), "r"(a[2]), "r"(a[3]), "r"(b[0]), "r"(b[1]));
}
// Fragment-order smem offsets, uint(half2) units, KT = K-extent/16.
template<int KT>
__device__ __forceinline__ int a_offT(int m, int k) {
    return (((m >> 4) * KT + (k >> 4)) * 32 + (m & 7) * 4 + ((k & 7) >> 1)) * 4
           + ((m >> 3) & 1) + 2 * ((k >> 3) & 1);
}
template<int KT>
__device__ __forceinline__ int b_offT(int k, int n) {
    return (((n >> 3) * KT + (k >> 4)) * 32 + (n & 7) * 4 + ((k & 7) >> 1)) * 2
           + ((k >> 3) & 1);
}
__device__ __forceinline__ int a_off(int m, int k) { return a_offT<2>(m, k); }
__device__ __forceinline__ int b_off(int k, int n) { return b_offT<2>(k, n); }

// ---------------------------------------------------------------------------
// FP16 tensor GEMM: 128 x BN CTA tile, KC=32 chunks, ping-pong smem + register
// prefetch. 256 threads, warps 4x2.  (unchanged from R12 — proven)
// ---------------------------------------------------------------------------
template<int BN, bool TB0, bool OH, bool RES>
__device__ __forceinline__ void gemm16(
    const __half* __restrict__ A, int ldA,
    const __half* __restrict__ B, int ldB,
    void* __restrict__ Cv, int ldC,
    const float* __restrict__ R,
    int K, float alpha)
{
    constexpr int NFRAG = BN / 16;
    __shared__ unsigned As[2][128 * 16];
    __shared__ unsigned Bs[2][BN * 16];
    const int tid  = threadIdx.x;
    const int lane = tid & 31, warp = tid >> 5;
    const int wm = warp >> 1, wn = warp & 1;
    const int m0 = blockIdx.y * 128, n0 = blockIdx.x * BN;

    uint4 pa[2], pb[2];
    constexpr int BIT = (BN * 32 / 8) / 256;

    auto loadA = [&](int k0) {
#pragma unroll
        for (int it = 0; it < 2; it++) {
            int idx = tid + it * 256;
            int m = idx >> 2, kq = (idx & 3) * 8;
            pa[it] = *(const uint4*)(A + (size_t)(m0 + m) * ldA + k0 + kq);
        }
    };
    auto loadB = [&](int k0) {
#pragma unroll
        for (int it = 0; it < BIT; it++) {
            int idx = tid + it * 256;
            if constexpr (!TB0) {
                int n = idx >> 2, kq = (idx & 3) * 8;
                pb[it] = *(const uint4*)(B + (size_t)(n0 + n) * ldB + k0 + kq);
            } else {
                int k = idx >> 3, nq = (idx & 7) * 8;
                pb[it] = *(const uint4*)(B + (size_t)(k0 + k) * ldB + n0 + nq);
            }
        }
    };
    auto stage = [&](int p) {
#pragma unroll
        for (int it = 0; it < 2; it++) {
            int idx = tid + it * 256;
            int m = idx >> 2, kq = (idx & 3) * 8;
            unsigned u[4] = {pa[it].x, pa[it].y, pa[it].z, pa[it].w};
#pragma unroll
            for (int j = 0; j < 4; j++) As[p][a_off(m, kq + 2 * j)] = u[j];
        }
#pragma unroll
        for (int it = 0; it < BIT; it++) {
            int idx = tid + it * 256;
            if constexpr (!TB0) {
                int n = idx >> 2, kq = (idx & 3) * 8;
                unsigned u[4] = {pb[it].x, pb[it].y, pb[it].z, pb[it].w};
#pragma unroll
                for (int j = 0; j < 4; j++) Bs[p][b_off(kq + 2 * j, n)] = u[j];
            } else {
                int k = idx >> 3, nq = (idx & 7) * 8;
                __half h[8];
                *(uint4*)h = pb[it];
                __half* Bh = (__half*)Bs[p];
#pragma unroll
                for (int j = 0; j < 8; j++)
                    Bh[b_off(k, nq + j) * 2 + (k & 1)] = h[j];
            }
        }
    };

    float acc[2][NFRAG][4] = {};
    int p = 0;
    loadA(0); loadB(0);
    stage(0);
    __syncthreads();

    for (int k0 = 0; k0 < K; k0 += 32) {
        bool more = (k0 + 32 < K);
        if (more) { loadA(k0 + 32); loadB(k0 + 32); }
#pragma unroll
        for (int ks = 0; ks < 2; ks++) {
            unsigned a[2][4], b[NFRAG][2];
#pragma unroll
            for (int mfi = 0; mfi < 2; mfi++) {
                uint4 t = *(const uint4*)&As[p][(((wm * 2 + mfi) * 2 + ks) * 32 + lane) * 4];
                a[mfi][0] = t.x; a[mfi][1] = t.y; a[mfi][2] = t.z; a[mfi][3] = t.w;
            }
#pragma unroll
            for (int nfi = 0; nfi < NFRAG; nfi++) {
                uint2 t = *(const uint2*)&Bs[p][(((wn * NFRAG + nfi) * 2 + ks) * 32 + lane) * 2];
                b[nfi][0] = t.x; b[nfi][1] = t.y;
            }
#pragma unroll
            for (int mfi = 0; mfi < 2; mfi++)
#pragma unroll
                for (int nfi = 0; nfi < NFRAG; nfi++)
                    mma16(acc[mfi][nfi], a[mfi], b[nfi]);
        }
        if (more) { stage(1 - p); p ^= 1; __syncthreads(); }
    }

    float* Cf = (float*)Cv;
    __half* Ch = (__half*)Cv;
#pragma unroll
    for (int mfi = 0; mfi < 2; mfi++) {
#pragma unroll
        for (int nfi = 0; nfi < NFRAG; nfi++) {
            int row = m0 + wm * 32 + mfi * 16 + (lane >> 2);
            int col = n0 + wn * (BN / 2) + nfi * 8 + (lane & 3) * 2;
            float2 v0 = make_float2(acc[mfi][nfi][0] * alpha, acc[mfi][nfi][1] * alpha);
            float2 v1 = make_float2(acc[mfi][nfi][2] * alpha, acc[mfi][nfi][3] * alpha);
            if constexpr (RES) {
                float2 r0 = *(const float2*)(R + (size_t)row * ldC + col);
                float2 r1 = *(const float2*)(R + (size_t)(row + 8) * ldC + col);
                v0.x += r0.x; v0.y += r0.y; v1.x += r1.x; v1.y += r1.y;
            }
            if constexpr (OH) {
                *(__half2*)(Ch + (size_t)row * ldC + col) = __floats2half2_rn(v0.x, v0.y);
                *(__half2*)(Ch + (size_t)(row + 8) * ldC + col) = __floats2half2_rn(v1.x, v1.y);
            } else {
                *(float2*)(Cf + (size_t)row * ldC + col) = v0;
                *(float2*)(Cf + (size_t)(row + 8) * ldC + col) = v1;
            }
        }
    }
}

// ---------------------------------------------------------------------------
// Fused flash attention: sim + softmax + PV in one kernel.
// Grid (8 qblocks, 64 bh), 256 threads. Warp w owns q-rows [w*16, w*16+16).
// Per thread: rows r = lane>>2 and r+8 of the warp tile.
// ---------------------------------------------------------------------------
__global__ void __launch_bounds__(256) k_flash() {
    __shared__ unsigned Kb[4096];   // Q staging (A,KT=4), then K tiles (B,KT=4)
    __shared__ unsigned Vb[4096];   // V tiles (B layout, KT=8)
    const int tid = threadIdx.x, warp = tid >> 5, lane = tid & 31;
    const int bh = blockIdx.y, b = bh >> 3, h = bh & 7;
    const int q0 = blockIdx.x * 128;
    const __half* qkv = g_qkvt + (size_t)b * NPIX * QKVC;
    const __half* Qg = qkv + h * 64;
    const __half* Kg = qkv + 512 + h * 64;
    const __half* Vg = qkv + 1024 + h * 64;

    // ---- stage Q (128 x 64) into A layout, pull warp's A-frags to registers
    {
#pragma unroll
        for (int it = 0; it < 4; it++) {
            int idx = tid + it * 256;
            int m = idx >> 3, kq = (idx & 7) * 8;
            uint4 v = *(const uint4*)(Qg + (size_t)(q0 + m) * QKVC + kq);
            unsigned u[4] = {v.x, v.y, v.z, v.w};
#pragma unroll
            for (int j = 0; j < 4; j++) Kb[a_offT<4>(m, kq + 2 * j)] = u[j];
        }
    }
    __syncthreads();
    unsigned a_q[4][4];
#pragma unroll
    for (int ki = 0; ki < 4; ki++) {
        uint4 t = *(const uint4*)&Kb[((warp * 4 + ki) * 32 + lane) * 4];
        a_q[ki][0] = t.x; a_q[ki][1] = t.y; a_q[ki][2] = t.z; a_q[ki][3] = t.w;
    }

    float acc_o[8][4] = {};
    float m0 = -1e30f, m1 = -1e30f, l0 = 0.f, l1 = 0.f;

    for (int kt = 0; kt < 8; kt++) {
        __syncthreads();   // prior-tile reads done (first iter: Q frags read)
        const int j0 = kt * 128;
        // stage K tile (128 keys x 64 d), B layout KT=4, n-major k-contig
#pragma unroll
        for (int it = 0; it < 4; it++) {
            int idx = tid + it * 256;
            int n = idx >> 3, kq = (idx & 7) * 8;
            uint4 v = *(const uint4*)(Kg + (size_t)(j0 + n) * QKVC + kq);
            unsigned u[4] = {v.x, v.y, v.z, v.w};
#pragma unroll
            for (int j = 0; j < 4; j++) Kb[b_offT<4>(kq + 2 * j, n)] = u[j];
        }
        // stage V tile (k=128 keys, n=64 d), B layout KT=8, k-major n-contig
        {
            __half* Vh = (__half*)Vb;
#pragma unroll
            for (int it = 0; it < 4; it++) {
                int idx = tid + it * 256;
                int k = idx >> 3, nq = (idx & 7) * 8;
                uint4 v = *(const uint4*)(Vg + (size_t)(j0 + k) * QKVC + nq);
                __half hh[8];
                *(uint4*)hh = v;
#pragma unroll
                for (int j = 0; j < 8; j++)
                    Vh[b_offT<8>(k, nq + j) * 2 + (k & 1)] = hh[j];
            }
        }
        __syncthreads();

        // ---- S = Q K^T  (warp: 16 rows x 128 keys)
        float s[16][4] = {};
#pragma unroll
        for (int ki = 0; ki < 4; ki++) {
            unsigned bb[16][2];
#pragma unroll
            for (int ni = 0; ni < 16; ni++) {
                uint2 t = *(const uint2*)&Kb[((ni * 4 + ki) * 32 + lane) * 2];
                bb[ni][0] = t.x; bb[ni][1] = t.y;
            }
#pragma unroll
            for (int ni = 0; ni < 16; ni++)
                mma16(s[ni], a_q[ki], bb[ni]);
        }

        // ---- online softmax
        float mx0 = -1e30f, mx1 = -1e30f;
#pragma unroll
        for (int ni = 0; ni < 16; ni++) {
#pragma unroll
            for (int j = 0; j < 4; j++) s[ni][j] *= SCALEF;
            mx0 = fmaxf(mx0, fmaxf(s[ni][0], s[ni][1]));
            mx1 = fmaxf(mx1, fmaxf(s[ni][2], s[ni][3]));
        }
        mx0 = fmaxf(mx0, __shfl_xor_sync(0xffffffffu, mx0, 1));
        mx0 = fmaxf(mx0, __shfl_xor_sync(0xffffffffu, mx0, 2));
        mx1 = fmaxf(mx1, __shfl_xor_sync(0xffffffffu, mx1, 1));
        mx1 = fmaxf(mx1, __shfl_xor_sync(0xffffffffu, mx1, 2));
        float nm0 = fmaxf(m0, mx0), nm1 = fmaxf(m1, mx1);
        float c0 = __expf(m0 - nm0), c1 = __expf(m1 - nm1);
        m0 = nm0; m1 = nm1;

        unsigned a_p[8][4];
        float sum0 = 0.f, sum1 = 0.f;
#pragma unroll
        for (int kf = 0; kf < 8; kf++) {
#pragma unroll
            for (int sub = 0; sub < 2; sub++) {
                int ni = 2 * kf + sub;
                float p0 = __expf(s[ni][0] - nm0);
                float p1 = __expf(s[ni][1] - nm0);
                float p2 = __expf(s[ni][2] - nm1);
                float p3 = __expf(s[ni][3] - nm1);
                sum0 += p0 + p1; sum1 += p2 + p3;
                __half2 h01 = __floats2half2_rn(p0, p1);
                __half2 h23 = __floats2half2_rn(p2, p3);
                a_p[kf][sub * 2]     = *(unsigned*)&h01;
                a_p[kf][sub * 2 + 1] = *(unsigned*)&h23;
            }
        }
        sum0 += __shfl_xor_sync(0xffffffffu, sum0, 1);
        sum0 += __shfl_xor_sync(0xffffffffu, sum0, 2);
        sum1 += __shfl_xor_sync(0xffffffffu, sum1, 1);
        sum1 += __shfl_xor_sync(0xffffffffu, sum1, 2);
        l0 = l0 * c0 + sum0;
        l1 = l1 * c1 + sum1;
#pragma unroll
        for (int ni = 0; ni < 8; ni++) {
            acc_o[ni][0] *= c0; acc_o[ni][1] *= c0;
            acc_o[ni][2] *= c1; acc_o[ni][3] *= c1;
        }

        // ---- O += P V  (k = 128 keys, n = 64 d)
#pragma unroll
        for (int kf = 0; kf < 8; kf++) {
            unsigned vv[8][2];
#pragma unroll
            for (int ni = 0; ni < 8; ni++) {
                uint2 t = *(const uint2*)&Vb[((ni * 8 + kf) * 32 + lane) * 2];
                vv[ni][0] = t.x; vv[ni][1] = t.y;
            }
#pragma unroll
            for (int ni = 0; ni < 8; ni++)
                mma16(acc_o[ni], a_p[kf], vv[ni]);
        }
    }

    // ---- epilogue
    float i0 = 1.0f / l0, i1 = 1.0f / l1;
    int row = q0 + warp * 16 + (lane >> 2);
    __half* Og = g_atth + (size_t)b * NPIX * CCH + h * 64;
#pragma unroll
    for (int ni = 0; ni < 8; ni++) {
        int col = ni * 8 + (lane & 3) * 2;
        *(__half2*)(Og + (size_t)row * CCH + col) =
            __floats2half2_rn(acc_o[ni][0] * i0, acc_o[ni][1] * i0);
        *(__half2*)(Og + (size_t)(row + 8) * CCH + col) =
            __floats2half2_rn(acc_o[ni][2] * i1, acc_o[ni][3] * i1);
    }
}

// ---------------------------------------------------------------------------
// GEMM wrappers (projection GEMMs unchanged)
// ---------------------------------------------------------------------------
__global__ void __launch_bounds__(256) k_qkv() {
    int b = blockIdx.z;
    gemm16<128, false, true, false>(
        g_xnh + (size_t)b * NPIX * CCH, CCH,
        g_wqkvh, CCH,
        g_qkvt + (size_t)b * NPIX * QKVC, QKVC, nullptr, CCH, 1.f);
}
__global__ void __launch_bounds__(256) k_out(const float* __restrict__ X,
                                             float* __restrict__ O) {
    int b = blockIdx.z;
    gemm16<128, false, false, true>(
        g_wouth, CCH,
        g_atth + (size_t)b * NPIX * CCH, CCH,
        O + (size_t)b * CCH * NPIX, NPIX,
        X + (size_t)b * CCH * NPIX, CCH, 1.f);
}

// ---------------------------------------------------------------------------
// Weight conversion fp32 -> fp16 (one-shot, tiny)
// ---------------------------------------------------------------------------
__global__ void wconv(const float* __restrict__ wq, const float* __restrict__ wo) {
    int i = blockIdx.x * 256 + threadIdx.x;
    if (i < QKVC * CCH) g_wqkvh[i] = __float2half_rn(wq[i]);
    if (i < CCH * CCH)  g_wouth[i] = __float2half_rn(wo[i]);
}

// ---------------------------------------------------------------------------
// Channel LayerNorm; writes g_xnh transposed [b][n][c] (half) via smem tile.
// ---------------------------------------------------------------------------
__global__ void ln_kernel(const float* __restrict__ x, const float* __restrict__ gamma) {
    int b = blockIdx.y, n0 = blockIdx.x * 32;
    int tx = threadIdx.x, ty = threadIdx.y;
    const float* xb = x + (size_t)b * CCH * NPIX + n0 + tx;

    float s = 0.f, s2 = 0.f;
    for (int c = ty; c < CCH; c += 8) {
        float v = xb[(size_t)c * NPIX];
        s += v; s2 += v * v;
    }
    __shared__ float sh1[8][32], sh2[8][32];
    sh1[ty][tx] = s; sh2[ty][tx] = s2;
    __syncthreads();
    float S = 0.f, S2 = 0.f;
#pragma unroll
    for (int r = 0; r < 8; r++) { S += sh1[r][tx]; S2 += sh2[r][tx]; }
    float mean = S * (1.f / CCH);
    float var  = S2 * (1.f / CCH) - mean * mean;
    float rstd = rsqrtf(var + EPSLN);

    __shared__ float tile[32][72];
    __half* xo = g_xnh + (size_t)b * NPIX * CCH;
    int tid = ty * 32 + tx;
    for (int c0 = 0; c0 < CCH; c0 += 64) {
#pragma unroll
        for (int j = 0; j < 8; j++) {
            int c = c0 + ty * 8 + j;
            tile[tx][ty * 8 + j] = (xb[(size_t)c * NPIX] - mean) * rstd * gamma[c];
        }
        __syncthreads();
        int row = tid >> 3, cq = (tid & 7) * 8;
        float4 a = *(float4*)&tile[row][cq];
        float4 bq = *(float4*)&tile[row][cq + 4];
        __half2 h[4] = {__floats2half2_rn(a.x, a.y),  __floats2half2_rn(a.z, a.w),
                        __floats2half2_rn(bq.x, bq.y), __floats2half2_rn(bq.z, bq.w)};
        *(uint4*)(xo + (size_t)(n0 + row) * CCH + c0 + cq) = *(uint4*)h;
        __syncthreads();
    }
}

// ---------------------------------------------------------------------------
extern "C" void kernel_launch(void* const* d_in, const int* in_sizes, int n_in,
                              void* d_out, int out_size) {
    const float* x     = (const float*)d_in[0];
    const float* gamma = (const float*)d_in[1];
    const float* w_qkv = (const float*)d_in[2];
    const float* w_out = (const float*)d_in[3];
    float* out = (float*)d_out;

    wconv<<<(QKVC * CCH + 255) / 256, 256>>>(w_qkv, w_out);
    ln_kernel<<<dim3(NPIX / 32, BATCH), dim3(32, 8)>>>(x, gamma);
    k_qkv<<<dim3(QKVC / 128, NPIX / 128, BATCH), 256>>>();
    k_flash<<<dim3(NPIX / 128, BHTOT), 256>>>();
    k_out<<<dim3(NPIX / 128, CCH / 128, BATCH), 256>>>(x, out);
}

// round 17
// speedup vs baseline: 1.6602x; 1.6602x over previous
#include <cuda_runtime.h>
#include <cuda_fp16.h>
#include <cstdint>

#define BATCH 8
#define CCH   512
#define NPIX  1024
#define QKVC  1536
#define BHTOT 64
#define EPSLN 1e-5f
#define SCALEF 0.125f

// Scratch (device globals: allocation-free contract)
__device__ __half g_xnh [(size_t)BATCH * NPIX * CCH];   // [b][n][c]  LN out (half)
__device__ __half g_qkvt[(size_t)BATCH * NPIX * QKVC];  // [b][n][o]  qkv^T (half)
__device__ __half g_atth[(size_t)BATCH * NPIX * CCH];   // [b][n][hc] attn out (half)
__device__ __half g_wqkvh[QKVC * CCH];
__device__ __half g_wouth[CCH * CCH];

// ---------------------------------------------------------------------------
// fp16 mma.sync helpers (fragment maps validated R10/R12/R16 on hardware)
// ---------------------------------------------------------------------------
__device__ __forceinline__ void mma16(float* c, const unsigned* a, const unsigned* b) {
    asm volatile("mma.sync.aligned.m16n8k16.row.col.f32.f16.f16.f32 "
        "{%0,%1,%2,%3}, {%4,%5,%6,%7}, {%8,%9}, {%0,%1,%2,%3};"
        : "+f"(c[0]), "+f"(c[1]), "+f"(c[2]), "+f"(c[3])
        : "r"(a[0]), "r"(a[1]), "r"(a[2]), "r"(a[3]), "r"(b[0]), "r"(b[1]));
}
// Fragment-order smem offsets, uint(half2) units, KT = K-extent/16.
template<int KT>
__device__ __forceinline__ int a_offT(int m, int k) {
    return (((m >> 4) * KT + (k >> 4)) * 32 + (m & 7) * 4 + ((k & 7) >> 1)) * 4
           + ((m >> 3) & 1) + 2 * ((k >> 3) & 1);
}
template<int KT>
__device__ __forceinline__ int b_offT(int k, int n) {
    return (((n >> 3) * KT + (k >> 4)) * 32 + (n & 7) * 4 + ((k & 7) >> 1)) * 2
           + ((k >> 3) & 1);
}
__device__ __forceinline__ int a_off(int m, int k) { return a_offT<2>(m, k); }
__device__ __forceinline__ int b_off(int k, int n) { return b_offT<2>(k, n); }

// ---------------------------------------------------------------------------
// FP16 tensor GEMM: 128 x BN CTA tile, KC=32 chunks, ping-pong smem + register
// prefetch. 256 threads, warps 4x2.  (unchanged from R12 — proven)
// ---------------------------------------------------------------------------
template<int BN, bool TB0, bool OH, bool RES>
__device__ __forceinline__ void gemm16(
    const __half* __restrict__ A, int ldA,
    const __half* __restrict__ B, int ldB,
    void* __restrict__ Cv, int ldC,
    const float* __restrict__ R,
    int K, float alpha)
{
    constexpr int NFRAG = BN / 16;
    __shared__ unsigned As[2][128 * 16];
    __shared__ unsigned Bs[2][BN * 16];
    const int tid  = threadIdx.x;
    const int lane = tid & 31, warp = tid >> 5;
    const int wm = warp >> 1, wn = warp & 1;
    const int m0 = blockIdx.y * 128, n0 = blockIdx.x * BN;

    uint4 pa[2], pb[2];
    constexpr int BIT = (BN * 32 / 8) / 256;

    auto loadA = [&](int k0) {
#pragma unroll
        for (int it = 0; it < 2; it++) {
            int idx = tid + it * 256;
            int m = idx >> 2, kq = (idx & 3) * 8;
            pa[it] = *(const uint4*)(A + (size_t)(m0 + m) * ldA + k0 + kq);
        }
    };
    auto loadB = [&](int k0) {
#pragma unroll
        for (int it = 0; it < BIT; it++) {
            int idx = tid + it * 256;
            if constexpr (!TB0) {
                int n = idx >> 2, kq = (idx & 3) * 8;
                pb[it] = *(const uint4*)(B + (size_t)(n0 + n) * ldB + k0 + kq);
            } else {
                int k = idx >> 3, nq = (idx & 7) * 8;
                pb[it] = *(const uint4*)(B + (size_t)(k0 + k) * ldB + n0 + nq);
            }
        }
    };
    auto stage = [&](int p) {
#pragma unroll
        for (int it = 0; it < 2; it++) {
            int idx = tid + it * 256;
            int m = idx >> 2, kq = (idx & 3) * 8;
            unsigned u[4] = {pa[it].x, pa[it].y, pa[it].z, pa[it].w};
#pragma unroll
            for (int j = 0; j < 4; j++) As[p][a_off(m, kq + 2 * j)] = u[j];
        }
#pragma unroll
        for (int it = 0; it < BIT; it++) {
            int idx = tid + it * 256;
            if constexpr (!TB0) {
                int n = idx >> 2, kq = (idx & 3) * 8;
                unsigned u[4] = {pb[it].x, pb[it].y, pb[it].z, pb[it].w};
#pragma unroll
                for (int j = 0; j < 4; j++) Bs[p][b_off(kq + 2 * j, n)] = u[j];
            } else {
                int k = idx >> 3, nq = (idx & 7) * 8;
                __half h[8];
                *(uint4*)h = pb[it];
                __half* Bh = (__half*)Bs[p];
#pragma unroll
                for (int j = 0; j < 8; j++)
                    Bh[b_off(k, nq + j) * 2 + (k & 1)] = h[j];
            }
        }
    };

    float acc[2][NFRAG][4] = {};
    int p = 0;
    loadA(0); loadB(0);
    stage(0);
    __syncthreads();

    for (int k0 = 0; k0 < K; k0 += 32) {
        bool more = (k0 + 32 < K);
        if (more) { loadA(k0 + 32); loadB(k0 + 32); }
#pragma unroll
        for (int ks = 0; ks < 2; ks++) {
            unsigned a[2][4], b[NFRAG][2];
#pragma unroll
            for (int mfi = 0; mfi < 2; mfi++) {
                uint4 t = *(const uint4*)&As[p][(((wm * 2 + mfi) * 2 + ks) * 32 + lane) * 4];
                a[mfi][0] = t.x; a[mfi][1] = t.y; a[mfi][2] = t.z; a[mfi][3] = t.w;
            }
#pragma unroll
            for (int nfi = 0; nfi < NFRAG; nfi++) {
                uint2 t = *(const uint2*)&Bs[p][(((wn * NFRAG + nfi) * 2 + ks) * 32 + lane) * 2];
                b[nfi][0] = t.x; b[nfi][1] = t.y;
            }
#pragma unroll
            for (int mfi = 0; mfi < 2; mfi++)
#pragma unroll
                for (int nfi = 0; nfi < NFRAG; nfi++)
                    mma16(acc[mfi][nfi], a[mfi], b[nfi]);
        }
        if (more) { stage(1 - p); p ^= 1; __syncthreads(); }
    }

    float* Cf = (float*)Cv;
    __half* Ch = (__half*)Cv;
#pragma unroll
    for (int mfi = 0; mfi < 2; mfi++) {
#pragma unroll
        for (int nfi = 0; nfi < NFRAG; nfi++) {
            int row = m0 + wm * 32 + mfi * 16 + (lane >> 2);
            int col = n0 + wn * (BN / 2) + nfi * 8 + (lane & 3) * 2;
            float2 v0 = make_float2(acc[mfi][nfi][0] * alpha, acc[mfi][nfi][1] * alpha);
            float2 v1 = make_float2(acc[mfi][nfi][2] * alpha, acc[mfi][nfi][3] * alpha);
            if constexpr (RES) {
                float2 r0 = *(const float2*)(R + (size_t)row * ldC + col);
                float2 r1 = *(const float2*)(R + (size_t)(row + 8) * ldC + col);
                v0.x += r0.x; v0.y += r0.y; v1.x += r1.x; v1.y += r1.y;
            }
            if constexpr (OH) {
                *(__half2*)(Ch + (size_t)row * ldC + col) = __floats2half2_rn(v0.x, v0.y);
                *(__half2*)(Ch + (size_t)(row + 8) * ldC + col) = __floats2half2_rn(v1.x, v1.y);
            } else {
                *(float2*)(Cf + (size_t)row * ldC + col) = v0;
                *(float2*)(Cf + (size_t)(row + 8) * ldC + col) = v1;
            }
        }
    }
}

// ---------------------------------------------------------------------------
// Fused flash attention v2: 64-key tiles, ping-pong smem, register prefetch,
// 1 sync/tile. __launch_bounds__(256,2) -> 2 CTAs/SM (16 warps).
// Grid (8 qblocks, 64 bh). Warp owns 16 q-rows; thread rows r=lane>>2, r+8.
// ---------------------------------------------------------------------------
__global__ void __launch_bounds__(256, 2) k_flash() {
    // sm[0..2047]     : K tile p=0   | Q staging uses sm[0..4095]
    // sm[2048..4095]  : K tile p=1
    // sm[4096..6143]  : V tile p=0
    // sm[6144..8191]  : V tile p=1
    __shared__ unsigned sm[8192];   // 32 KB
    const int tid = threadIdx.x, warp = tid >> 5, lane = tid & 31;
    const int bh = blockIdx.y, b = bh >> 3, h = bh & 7;
    const int q0 = blockIdx.x * 128;
    const __half* qkv = g_qkvt + (size_t)b * NPIX * QKVC;
    const __half* Qg = qkv + h * 64;
    const __half* Kg = qkv + 512 + h * 64;
    const __half* Vg = qkv + 1024 + h * 64;

    // ---- stage Q (128 x 64) into A layout (KT=4), pull warp frags
#pragma unroll
    for (int it = 0; it < 4; it++) {
        int idx = tid + it * 256;
        int m = idx >> 3, kq = (idx & 7) * 8;
        uint4 v = *(const uint4*)(Qg + (size_t)(q0 + m) * QKVC + kq);
        unsigned u[4] = {v.x, v.y, v.z, v.w};
#pragma unroll
        for (int j = 0; j < 4; j++) sm[a_offT<4>(m, kq + 2 * j)] = u[j];
    }
    __syncthreads();
    unsigned a_q[4][4];
#pragma unroll
    for (int ki = 0; ki < 4; ki++) {
        uint4 t = *(const uint4*)&sm[((warp * 4 + ki) * 32 + lane) * 4];
        a_q[ki][0] = t.x; a_q[ki][1] = t.y; a_q[ki][2] = t.z; a_q[ki][3] = t.w;
    }
    __syncthreads();   // Q region free for K tiles

    uint4 pk[2], pv[2];
    auto loadKV = [&](int j0) {
#pragma unroll
        for (int it = 0; it < 2; it++) {
            int idx = tid + it * 256;
            int r = idx >> 3, cq = (idx & 7) * 8;
            pk[it] = *(const uint4*)(Kg + (size_t)(j0 + r) * QKVC + cq);
            pv[it] = *(const uint4*)(Vg + (size_t)(j0 + r) * QKVC + cq);
        }
    };
    auto stageKV = [&](int p) {
        unsigned* Ksm = sm + p * 2048;
        __half*   Vh  = (__half*)(sm + 4096 + p * 2048);
#pragma unroll
        for (int it = 0; it < 2; it++) {
            int idx = tid + it * 256;
            int r = idx >> 3, cq = (idx & 7) * 8;
            // K: key r is B-frag n index, d is k
            unsigned u[4] = {pk[it].x, pk[it].y, pk[it].z, pk[it].w};
#pragma unroll
            for (int j = 0; j < 4; j++) Ksm[b_offT<4>(cq + 2 * j, r)] = u[j];
            // V: key r is B-frag k index, d is n
            __half hh[8];
            *(uint4*)hh = pv[it];
#pragma unroll
            for (int j = 0; j < 8; j++)
                Vh[b_offT<4>(r, cq + j) * 2 + (r & 1)] = hh[j];
        }
    };

    float acc_o[8][4] = {};
    float m0 = -1e30f, m1 = -1e30f, l0 = 0.f, l1 = 0.f;

    loadKV(0);
    stageKV(0);
    __syncthreads();
    int p = 0;

    for (int kt = 0; kt < 16; kt++) {
        bool more = (kt + 1 < 16);
        if (more) loadKV((kt + 1) * 64);

        const unsigned* Ksm = sm + p * 2048;
        const unsigned* Vsm = sm + 4096 + p * 2048;

        // ---- S = Q K^T  (warp: 16 rows x 64 keys)
        float s[8][4] = {};
#pragma unroll
        for (int ki = 0; ki < 4; ki++) {
            unsigned bb[8][2];
#pragma unroll
            for (int ni = 0; ni < 8; ni++) {
                uint2 t = *(const uint2*)&Ksm[((ni * 4 + ki) * 32 + lane) * 2];
                bb[ni][0] = t.x; bb[ni][1] = t.y;
            }
#pragma unroll
            for (int ni = 0; ni < 8; ni++)
                mma16(s[ni], a_q[ki], bb[ni]);
        }

        // ---- online softmax
        float mx0 = -1e30f, mx1 = -1e30f;
#pragma unroll
        for (int ni = 0; ni < 8; ni++) {
#pragma unroll
            for (int j = 0; j < 4; j++) s[ni][j] *= SCALEF;
            mx0 = fmaxf(mx0, fmaxf(s[ni][0], s[ni][1]));
            mx1 = fmaxf(mx1, fmaxf(s[ni][2], s[ni][3]));
        }
        mx0 = fmaxf(mx0, __shfl_xor_sync(0xffffffffu, mx0, 1));
        mx0 = fmaxf(mx0, __shfl_xor_sync(0xffffffffu, mx0, 2));
        mx1 = fmaxf(mx1, __shfl_xor_sync(0xffffffffu, mx1, 1));
        mx1 = fmaxf(mx1, __shfl_xor_sync(0xffffffffu, mx1, 2));
        float nm0 = fmaxf(m0, mx0), nm1 = fmaxf(m1, mx1);
        float c0 = __expf(m0 - nm0), c1 = __expf(m1 - nm1);
        m0 = nm0; m1 = nm1;

        unsigned a_p[4][4];
        float sum0 = 0.f, sum1 = 0.f;
#pragma unroll
        for (int kf = 0; kf < 4; kf++) {
#pragma unroll
            for (int sub = 0; sub < 2; sub++) {
                int ni = 2 * kf + sub;
                float p0 = __expf(s[ni][0] - nm0);
                float p1 = __expf(s[ni][1] - nm0);
                float p2 = __expf(s[ni][2] - nm1);
                float p3 = __expf(s[ni][3] - nm1);
                sum0 += p0 + p1; sum1 += p2 + p3;
                __half2 h01 = __floats2half2_rn(p0, p1);
                __half2 h23 = __floats2half2_rn(p2, p3);
                a_p[kf][sub * 2]     = *(unsigned*)&h01;
                a_p[kf][sub * 2 + 1] = *(unsigned*)&h23;
            }
        }
        sum0 += __shfl_xor_sync(0xffffffffu, sum0, 1);
        sum0 += __shfl_xor_sync(0xffffffffu, sum0, 2);
        sum1 += __shfl_xor_sync(0xffffffffu, sum1, 1);
        sum1 += __shfl_xor_sync(0xffffffffu, sum1, 2);
        l0 = l0 * c0 + sum0;
        l1 = l1 * c1 + sum1;
#pragma unroll
        for (int ni = 0; ni < 8; ni++) {
            acc_o[ni][0] *= c0; acc_o[ni][1] *= c0;
            acc_o[ni][2] *= c1; acc_o[ni][3] *= c1;
        }

        // ---- O += P V  (k = 64 keys, n = 64 d)
#pragma unroll
        for (int kf = 0; kf < 4; kf++) {
            unsigned vv[8][2];
#pragma unroll
            for (int ni = 0; ni < 8; ni++) {
                uint2 t = *(const uint2*)&Vsm[((ni * 4 + kf) * 32 + lane) * 2];
                vv[ni][0] = t.x; vv[ni][1] = t.y;
            }
#pragma unroll
            for (int ni = 0; ni < 8; ni++)
                mma16(acc_o[ni], a_p[kf], vv[ni]);
        }

        if (more) { stageKV(1 - p); p ^= 1; __syncthreads(); }
    }

    // ---- epilogue
    float i0 = 1.0f / l0, i1 = 1.0f / l1;
    int row = q0 + warp * 16 + (lane >> 2);
    __half* Og = g_atth + (size_t)b * NPIX * CCH + h * 64;
#pragma unroll
    for (int ni = 0; ni < 8; ni++) {
        int col = ni * 8 + (lane & 3) * 2;
        *(__half2*)(Og + (size_t)row * CCH + col) =
            __floats2half2_rn(acc_o[ni][0] * i0, acc_o[ni][1] * i0);
        *(__half2*)(Og + (size_t)(row + 8) * CCH + col) =
            __floats2half2_rn(acc_o[ni][2] * i1, acc_o[ni][3] * i1);
    }
}

// ---------------------------------------------------------------------------
// GEMM wrappers (projection GEMMs unchanged)
// ---------------------------------------------------------------------------
__global__ void __launch_bounds__(256) k_qkv() {
    int b = blockIdx.z;
    gemm16<128, false, true, false>(
        g_xnh + (size_t)b * NPIX * CCH, CCH,
        g_wqkvh, CCH,
        g_qkvt + (size_t)b * NPIX * QKVC, QKVC, nullptr, CCH, 1.f);
}
__global__ void __launch_bounds__(256) k_out(const float* __restrict__ X,
                                             float* __restrict__ O) {
    int b = blockIdx.z;
    gemm16<128, false, false, true>(
        g_wouth, CCH,
        g_atth + (size_t)b * NPIX * CCH, CCH,
        O + (size_t)b * CCH * NPIX, NPIX,
        X + (size_t)b * CCH * NPIX, CCH, 1.f);
}

// ---------------------------------------------------------------------------
// Weight conversion fp32 -> fp16 (one-shot, tiny)
// ---------------------------------------------------------------------------
__global__ void wconv(const float* __restrict__ wq, const float* __restrict__ wo) {
    int i = blockIdx.x * 256 + threadIdx.x;
    if (i < QKVC * CCH) g_wqkvh[i] = __float2half_rn(wq[i]);
    if (i < CCH * CCH)  g_wouth[i] = __float2half_rn(wo[i]);
}

// ---------------------------------------------------------------------------
// Channel LayerNorm; writes g_xnh transposed [b][n][c] (half) via smem tile.
// ---------------------------------------------------------------------------
__global__ void ln_kernel(const float* __restrict__ x, const float* __restrict__ gamma) {
    int b = blockIdx.y, n0 = blockIdx.x * 32;
    int tx = threadIdx.x, ty = threadIdx.y;
    const float* xb = x + (size_t)b * CCH * NPIX + n0 + tx;

    float s = 0.f, s2 = 0.f;
    for (int c = ty; c < CCH; c += 8) {
        float v = xb[(size_t)c * NPIX];
        s += v; s2 += v * v;
    }
    __shared__ float sh1[8][32], sh2[8][32];
    sh1[ty][tx] = s; sh2[ty][tx] = s2;
    __syncthreads();
    float S = 0.f, S2 = 0.f;
#pragma unroll
    for (int r = 0; r < 8; r++) { S += sh1[r][tx]; S2 += sh2[r][tx]; }
    float mean = S * (1.f / CCH);
    float var  = S2 * (1.f / CCH) - mean * mean;
    float rstd = rsqrtf(var + EPSLN);

    __shared__ float tile[32][72];
    __half* xo = g_xnh + (size_t)b * NPIX * CCH;
    int tid = ty * 32 + tx;
    for (int c0 = 0; c0 < CCH; c0 += 64) {
#pragma unroll
        for (int j = 0; j < 8; j++) {
            int c = c0 + ty * 8 + j;
            tile[tx][ty * 8 + j] = (xb[(size_t)c * NPIX] - mean) * rstd * gamma[c];
        }
        __syncthreads();
        int row = tid >> 3, cq = (tid & 7) * 8;
        float4 a = *(float4*)&tile[row][cq];
        float4 bq = *(float4*)&tile[row][cq + 4];
        __half2 h[4] = {__floats2half2_rn(a.x, a.y),  __floats2half2_rn(a.z, a.w),
                        __floats2half2_rn(bq.x, bq.y), __floats2half2_rn(bq.z, bq.w)};
        *(uint4*)(xo + (size_t)(n0 + row) * CCH + c0 + cq) = *(uint4*)h;
        __syncthreads();
    }
}

// ---------------------------------------------------------------------------
extern "C" void kernel_launch(void* const* d_in, const int* in_sizes, int n_in,
                              void* d_out, int out_size) {
    const float* x     = (const float*)d_in[0];
    const float* gamma = (const float*)d_in[1];
    const float* w_qkv = (const float*)d_in[2];
    const float* w_out = (const float*)d_in[3];
    float* out = (float*)d_out;

    wconv<<<(QKVC * CCH + 255) / 256, 256>>>(w_qkv, w_out);
    ln_kernel<<<dim3(NPIX / 32, BATCH), dim3(32, 8)>>>(x, gamma);
    k_qkv<<<dim3(QKVC / 128, NPIX / 128, BATCH), 256>>>();
    k_flash<<<dim3(NPIX / 128, BHTOT), 256>>>();
    k_out<<<dim3(NPIX / 128, CCH / 128, BATCH), 256>>>(x, out);
}